// round 6
// baseline (speedup 1.0000x reference)
#include <cuda_runtime.h>
#include <cuda_bf16.h>

#define NMAX 50000
#define D    96
#define DEG_CAP 128   // Poisson(16) max over 50K nodes << 128

// Scratch (device globals; zero-initialized at load; g_deg restored to 0 by
// transform_kernel after each use, so every graph replay sees a clean state)
__device__ int g_deg[NMAX];
__device__ int g_adj[NMAX * DEG_CAP];   // padded adjacency (src lists per dst)

// ---------------------------------------------------------------------------
// Kernel 1: build padded adjacency. One thread per edge; int atomics.
// ---------------------------------------------------------------------------
__global__ void fill_kernel(const int* __restrict__ edge_index, int e_total) {
    int e = blockIdx.x * blockDim.x + threadIdx.x;
    if (e >= e_total) return;
    int src = __ldg(&edge_index[e]);
    int dst = __ldg(&edge_index[e_total + e]);
    int pos = atomicAdd(&g_deg[dst], 1);
    if (pos < DEG_CAP) g_adj[dst * DEG_CAP + pos] = src;
}

// ---------------------------------------------------------------------------
// f32x2 helpers (Blackwell packed fp32 — FFMA2 in SASS)
// ---------------------------------------------------------------------------
__device__ __forceinline__ unsigned long long pack2(float lo, float hi) {
    unsigned long long r;
    asm("mov.b64 %0, {%1, %2};" : "=l"(r) : "f"(lo), "f"(hi));
    return r;
}
__device__ __forceinline__ void unpack2(unsigned long long v, float& lo, float& hi) {
    asm("mov.b64 {%0, %1}, %2;" : "=f"(lo), "=f"(hi) : "l"(v));
}
__device__ __forceinline__ void fma2(unsigned long long& acc,
                                     unsigned long long a,
                                     unsigned long long b) {
    asm("fma.rn.f32x2 %0, %1, %2, %0;" : "+l"(acc) : "l"(a), "l"(b));
}

// ---------------------------------------------------------------------------
// Kernel 2: fused gather-mean + dual GEMM (FFMA2) + bias + ReLU.
// CTA = 64 nodes x 96 outputs, 256 threads, 2 CTAs/SM.
// ---------------------------------------------------------------------------
#define TILE_M 64
#define TM 4
#define TN 6
#define TNP 3           // TN/2 packed pairs
#define IN_STRIDE 100   // floats; %4==0 -> float4-aligned rows, conflict-free
#define W_STRIDE  98    // floats; even -> LDS.64-aligned pairs, conflict-free

__global__ __launch_bounds__(256, 2)
void transform_kernel(const float* __restrict__ x,
                      const float* __restrict__ Wl,
                      const float* __restrict__ bl,
                      const float* __restrict__ Wr,
                      float* __restrict__ out,
                      int n_total) {
    __shared__ float sA[TILE_M * IN_STRIDE];   // mean-aggregated neighbor feats
    __shared__ float sX[TILE_M * IN_STRIDE];   // root feats
    __shared__ float sW[D * W_STRIDE];         // W^T (k-major), per phase

    const int tid  = threadIdx.x;
    const int lane = tid & 31;
    const int warp = tid >> 5;
    const int base = blockIdx.x * TILE_M;

    // ---- load root features (coalesced float4) ----
    for (int i = tid; i < TILE_M * (D / 4); i += 256) {
        int m = i / 24;
        int c = i - m * 24;
        int node = base + m;
        float4 v = make_float4(0.f, 0.f, 0.f, 0.f);
        if (node < n_total)
            v = ((const float4*)(x + (size_t)node * D))[c];
        *(float4*)&sX[m * IN_STRIDE + c * 4] = v;
    }

    // ---- gather + mean into sA; zero g_deg for next run ----
    for (int m = warp; m < TILE_M; m += 8) {
        int node = base + m;
        int d = (node < n_total) ? g_deg[node] : 0;
        int dc = min(d, DEG_CAP);
        const int* adj = g_adj + (size_t)(node < n_total ? node : 0) * DEG_CAP;

        float4 s0 = make_float4(0.f, 0.f, 0.f, 0.f);
        float4 s1 = make_float4(0.f, 0.f, 0.f, 0.f);

        int nbr = (lane < dc) ? adj[lane] : 0;
        for (int jb = 0; jb < dc; jb += 32) {
            int cnt = min(32, dc - jb);
            int nxt = 0;
            int rem = dc - jb - 32;
            if (rem > 0 && lane < rem) nxt = adj[jb + 32 + lane];

            int j = 0;
            for (; j + 3 < cnt; j += 4) {
                int n0 = __shfl_sync(0xffffffffu, nbr, j);
                int n1 = __shfl_sync(0xffffffffu, nbr, j + 1);
                int n2 = __shfl_sync(0xffffffffu, nbr, j + 2);
                int n3 = __shfl_sync(0xffffffffu, nbr, j + 3);
                if (lane < 24) {
                    float4 v0 = ((const float4*)(x + (size_t)n0 * D))[lane];
                    float4 v1 = ((const float4*)(x + (size_t)n1 * D))[lane];
                    float4 v2 = ((const float4*)(x + (size_t)n2 * D))[lane];
                    float4 v3 = ((const float4*)(x + (size_t)n3 * D))[lane];
                    s0.x += v0.x; s0.y += v0.y; s0.z += v0.z; s0.w += v0.w;
                    s1.x += v1.x; s1.y += v1.y; s1.z += v1.z; s1.w += v1.w;
                    s0.x += v2.x; s0.y += v2.y; s0.z += v2.z; s0.w += v2.w;
                    s1.x += v3.x; s1.y += v3.y; s1.z += v3.z; s1.w += v3.w;
                }
            }
            for (; j < cnt; j++) {
                int n0 = __shfl_sync(0xffffffffu, nbr, j);
                if (lane < 24) {
                    float4 v0 = ((const float4*)(x + (size_t)n0 * D))[lane];
                    s0.x += v0.x; s0.y += v0.y; s0.z += v0.z; s0.w += v0.w;
                }
            }
            nbr = nxt;
        }

        float inv = __fdividef(1.f, fmaxf((float)d, 1.f));
        if (lane < 24) {
            float4 r;
            r.x = (s0.x + s1.x) * inv;
            r.y = (s0.y + s1.y) * inv;
            r.z = (s0.z + s1.z) * inv;
            r.w = (s0.w + s1.w) * inv;
            *(float4*)&sA[m * IN_STRIDE + lane * 4] = r;
        }
        // restore clean state for the next kernel_launch replay
        if (lane == 0 && node < n_total) g_deg[node] = 0;
    }

    // ---- dual GEMM with packed f32x2 FMA ----
    unsigned long long acc[TM][TNP];
#pragma unroll
    for (int i = 0; i < TM; i++)
#pragma unroll
        for (int p = 0; p < TNP; p++) acc[i][p] = 0ull;

    const int tx = tid & 15;
    const int ty = tid >> 4;
    const int o0 = tx * TN;    // even (TN=6) -> 8B-aligned W pairs
    const int m0 = ty * TM;

#pragma unroll 1
    for (int phase = 0; phase < 2; phase++) {
        const float* W = (phase == 0) ? Wl : Wr;
        __syncthreads();   // phase 0: sA/sX ready; phase 1: prev compute done
        for (int i = tid; i < D * D; i += 256) {
            int o = i / D;
            int k = i - o * D;
            sW[k * W_STRIDE + o] = W[i];
        }
        __syncthreads();

        const float* sIn = (phase == 0) ? sA : sX;

#pragma unroll 2
        for (int k = 0; k < D; k += 4) {
            float4 av[TM];
#pragma unroll
            for (int i = 0; i < TM; i++)
                av[i] = *(const float4*)&sIn[(m0 + i) * IN_STRIDE + k];

#pragma unroll
            for (int kk = 0; kk < 4; kk++) {
                const float* wr = &sW[(k + kk) * W_STRIDE + o0];
                unsigned long long w0 = *(const unsigned long long*)(wr);
                unsigned long long w1 = *(const unsigned long long*)(wr + 2);
                unsigned long long w2 = *(const unsigned long long*)(wr + 4);
#pragma unroll
                for (int i = 0; i < TM; i++) {
                    float a = (kk == 0) ? av[i].x : (kk == 1) ? av[i].y
                            : (kk == 2) ? av[i].z : av[i].w;
                    unsigned long long aa = pack2(a, a);
                    fma2(acc[i][0], aa, w0);
                    fma2(acc[i][1], aa, w1);
                    fma2(acc[i][2], aa, w2);
                }
            }
        }
    }

    // ---- epilogue: bias + relu + store ----
    float b[TN];
#pragma unroll
    for (int j = 0; j < TN; j++) b[j] = __ldg(&bl[o0 + j]);

#pragma unroll
    for (int i = 0; i < TM; i++) {
        int node = base + m0 + i;
        if (node < n_total) {
            float r[TN];
#pragma unroll
            for (int p = 0; p < TNP; p++)
                unpack2(acc[i][p], r[2 * p], r[2 * p + 1]);
            float* op = out + (size_t)node * D + o0;
#pragma unroll
            for (int j = 0; j < TN; j++)
                op[j] = fmaxf(r[j] + b[j], 0.f);
        }
    }
}

// ---------------------------------------------------------------------------
extern "C" void kernel_launch(void* const* d_in, const int* in_sizes, int n_in,
                              void* d_out, int out_size) {
    const float* x   = (const float*)d_in[0];   // [N, 96]
    const int*   ei  = (const int*)d_in[1];     // [2, E]
    const float* Wl  = (const float*)d_in[2];   // [96, 96]
    const float* bl  = (const float*)d_in[3];   // [96]
    const float* Wr  = (const float*)d_in[4];   // [96, 96]
    float* out = (float*)d_out;

    int n = in_sizes[0] / D;
    int e = in_sizes[1] / 2;

    fill_kernel<<<(e + 255) / 256, 256>>>(ei, e);
    transform_kernel<<<(n + TILE_M - 1) / TILE_M, 256>>>(x, Wl, bl, Wr, out, n);
}

// round 12
// speedup vs baseline: 1.3017x; 1.3017x over previous
#include <cuda_runtime.h>
#include <cuda_bf16.h>

#define NMAX 50000
#define D    96
#define DEG_CAP 128   // Poisson(16) max over 50K nodes << 128

// Scratch (device globals; zero-initialized at load; g_deg reset to 0 by
// gather_kernel after use, so every graph replay sees a clean state)
__device__ int   g_deg[NMAX];
__device__ int   g_adj[NMAX * DEG_CAP];   // padded adjacency (src per dst)
__device__ float g_agg[NMAX * D];         // mean-aggregated neighbor features

// ---------------------------------------------------------------------------
// Kernel 1: build padded adjacency. One thread per edge; int atomics.
// ---------------------------------------------------------------------------
__global__ void fill_kernel(const int* __restrict__ edge_index, int e_total) {
    int e = blockIdx.x * blockDim.x + threadIdx.x;
    if (e >= e_total) return;
    int src = __ldg(&edge_index[e]);
    int dst = __ldg(&edge_index[e_total + e]);
    int pos = atomicAdd(&g_deg[dst], 1);
    if (pos < DEG_CAP) g_adj[dst * DEG_CAP + pos] = src;
}

// ---------------------------------------------------------------------------
// Kernel 2: gather + mean. One warp per node; lanes 0..23 own one float4
// chunk of the 96-dim row. No smem, low regs -> full occupancy; the 4-deep
// unrolled gathers give enough MLP to run at the LTS throughput floor.
// Resets g_deg for the next replay.
// ---------------------------------------------------------------------------
__global__ __launch_bounds__(256)
void gather_kernel(const float* __restrict__ x, int n_total) {
    int gw   = (blockIdx.x * blockDim.x + threadIdx.x) >> 5;
    int lane = threadIdx.x & 31;
    if (gw >= n_total) return;
    int node = gw;

    int d  = g_deg[node];
    int dc = min(d, DEG_CAP);
    const int* adj = g_adj + (size_t)node * DEG_CAP;

    float4 s0 = make_float4(0.f, 0.f, 0.f, 0.f);
    float4 s1 = make_float4(0.f, 0.f, 0.f, 0.f);

    int nbr = (lane < dc) ? adj[lane] : 0;
    for (int jb = 0; jb < dc; jb += 32) {
        int cnt = min(32, dc - jb);
        int nxt = 0;
        int rem = dc - jb - 32;
        if (rem > 0 && lane < rem) nxt = adj[jb + 32 + lane];

        int j = 0;
        for (; j + 3 < cnt; j += 4) {
            int n0 = __shfl_sync(0xffffffffu, nbr, j);
            int n1 = __shfl_sync(0xffffffffu, nbr, j + 1);
            int n2 = __shfl_sync(0xffffffffu, nbr, j + 2);
            int n3 = __shfl_sync(0xffffffffu, nbr, j + 3);
            if (lane < 24) {
                float4 v0 = ((const float4*)(x + (size_t)n0 * D))[lane];
                float4 v1 = ((const float4*)(x + (size_t)n1 * D))[lane];
                float4 v2 = ((const float4*)(x + (size_t)n2 * D))[lane];
                float4 v3 = ((const float4*)(x + (size_t)n3 * D))[lane];
                s0.x += v0.x; s0.y += v0.y; s0.z += v0.z; s0.w += v0.w;
                s1.x += v1.x; s1.y += v1.y; s1.z += v1.z; s1.w += v1.w;
                s0.x += v2.x; s0.y += v2.y; s0.z += v2.z; s0.w += v2.w;
                s1.x += v3.x; s1.y += v3.y; s1.z += v3.z; s1.w += v3.w;
            }
        }
        for (; j < cnt; j++) {
            int n0 = __shfl_sync(0xffffffffu, nbr, j);
            if (lane < 24) {
                float4 v0 = ((const float4*)(x + (size_t)n0 * D))[lane];
                s0.x += v0.x; s0.y += v0.y; s0.z += v0.z; s0.w += v0.w;
            }
        }
        nbr = nxt;
    }

    float inv = __fdividef(1.f, fmaxf((float)d, 1.f));
    if (lane < 24) {
        float4 r;
        r.x = (s0.x + s1.x) * inv;
        r.y = (s0.y + s1.y) * inv;
        r.z = (s0.z + s1.z) * inv;
        r.w = (s0.w + s1.w) * inv;
        ((float4*)(g_agg + (size_t)node * D))[lane] = r;
    }
    if (lane == 0) g_deg[node] = 0;   // clean state for next replay
}

// ---------------------------------------------------------------------------
// f32x2 helpers (Blackwell packed fp32 — FFMA2 in SASS)
// ---------------------------------------------------------------------------
__device__ __forceinline__ unsigned long long pack2(float lo, float hi) {
    unsigned long long r;
    asm("mov.b64 %0, {%1, %2};" : "=l"(r) : "f"(lo), "f"(hi));
    return r;
}
__device__ __forceinline__ void unpack2(unsigned long long v, float& lo, float& hi) {
    asm("mov.b64 {%0, %1}, %2;" : "=f"(lo), "=f"(hi) : "l"(v));
}
__device__ __forceinline__ void fma2(unsigned long long& acc,
                                     unsigned long long a,
                                     unsigned long long b) {
    asm("fma.rn.f32x2 %0, %1, %2, %0;" : "+l"(acc) : "l"(a), "l"(b));
}

// ---------------------------------------------------------------------------
// Kernel 3: dual GEMM (FFMA2) + bias + ReLU.
// CTA = 64 nodes x 96 outputs, 256 threads. Input tile reloaded per phase
// (agg then x) into one buffer -> 63KB smem, 3 CTAs/SM.
// ---------------------------------------------------------------------------
#define TILE_M 64
#define TM 4
#define TN 6
#define TNP 3           // TN/2 packed pairs
#define IN_STRIDE 100   // floats; %4==0 -> float4-aligned rows, conflict-free
#define W_STRIDE  98    // floats; even -> LDS.64-aligned pairs, conflict-free

__global__ __launch_bounds__(256, 3)
void gemm_kernel(const float* __restrict__ x,
                 const float* __restrict__ Wl,
                 const float* __restrict__ bl,
                 const float* __restrict__ Wr,
                 float* __restrict__ out,
                 int n_total) {
    __shared__ float sIn[TILE_M * IN_STRIDE];  // 25.6 KB, reused per phase
    __shared__ float sW[D * W_STRIDE];         // 37.6 KB, reloaded per phase

    const int tid  = threadIdx.x;
    const int base = blockIdx.x * TILE_M;

    const int tx = tid & 15;
    const int ty = tid >> 4;
    const int o0 = tx * TN;    // even -> 8B-aligned W pairs
    const int m0 = ty * TM;

    unsigned long long acc[TM][TNP];
#pragma unroll
    for (int i = 0; i < TM; i++)
#pragma unroll
        for (int p = 0; p < TNP; p++) acc[i][p] = 0ull;

#pragma unroll 1
    for (int phase = 0; phase < 2; phase++) {
        const float* W  = (phase == 0) ? Wl : Wr;
        const float* In = (phase == 0) ? g_agg : x;

        __syncthreads();   // phase 1: previous compute done before overwrite

        // load input tile (coalesced float4)
        for (int i = tid; i < TILE_M * (D / 4); i += 256) {
            int m = i / 24;
            int c = i - m * 24;
            int node = base + m;
            float4 v = make_float4(0.f, 0.f, 0.f, 0.f);
            if (node < n_total)
                v = ((const float4*)(In + (size_t)node * D))[c];
            *(float4*)&sIn[m * IN_STRIDE + c * 4] = v;
        }
        // load W transposed: sW[k][o] = W[o*D + k]
        for (int i = tid; i < D * D; i += 256) {
            int o = i / D;
            int k = i - o * D;
            sW[k * W_STRIDE + o] = W[i];
        }
        __syncthreads();

#pragma unroll 2
        for (int k = 0; k < D; k += 4) {
            float4 av[TM];
#pragma unroll
            for (int i = 0; i < TM; i++)
                av[i] = *(const float4*)&sIn[(m0 + i) * IN_STRIDE + k];

#pragma unroll
            for (int kk = 0; kk < 4; kk++) {
                const float* wr = &sW[(k + kk) * W_STRIDE + o0];
                unsigned long long w0 = *(const unsigned long long*)(wr);
                unsigned long long w1 = *(const unsigned long long*)(wr + 2);
                unsigned long long w2 = *(const unsigned long long*)(wr + 4);
#pragma unroll
                for (int i = 0; i < TM; i++) {
                    float a = (kk == 0) ? av[i].x : (kk == 1) ? av[i].y
                            : (kk == 2) ? av[i].z : av[i].w;
                    unsigned long long aa = pack2(a, a);
                    fma2(acc[i][0], aa, w0);
                    fma2(acc[i][1], aa, w1);
                    fma2(acc[i][2], aa, w2);
                }
            }
        }
    }

    // epilogue: bias + relu + store
    float b[TN];
#pragma unroll
    for (int j = 0; j < TN; j++) b[j] = __ldg(&bl[o0 + j]);

#pragma unroll
    for (int i = 0; i < TM; i++) {
        int node = base + m0 + i;
        if (node < n_total) {
            float r[TN];
#pragma unroll
            for (int p = 0; p < TNP; p++)
                unpack2(acc[i][p], r[2 * p], r[2 * p + 1]);
            float* op = out + (size_t)node * D + o0;
#pragma unroll
            for (int j = 0; j < TN; j++)
                op[j] = fmaxf(r[j] + b[j], 0.f);
        }
    }
}

// ---------------------------------------------------------------------------
extern "C" void kernel_launch(void* const* d_in, const int* in_sizes, int n_in,
                              void* d_out, int out_size) {
    const float* x   = (const float*)d_in[0];   // [N, 96]
    const int*   ei  = (const int*)d_in[1];     // [2, E]
    const float* Wl  = (const float*)d_in[2];   // [96, 96]
    const float* bl  = (const float*)d_in[3];   // [96]
    const float* Wr  = (const float*)d_in[4];   // [96, 96]
    float* out = (float*)d_out;

    int n = in_sizes[0] / D;
    int e = in_sizes[1] / 2;

    fill_kernel<<<(e + 255) / 256, 256>>>(ei, e);
    gather_kernel<<<(n * 32 + 255) / 256, 256>>>(x, n);
    gemm_kernel<<<(n + TILE_M - 1) / TILE_M, 256>>>(x, Wl, bl, Wr, out, n);
}

// round 13
// speedup vs baseline: 1.3050x; 1.0025x over previous
#include <cuda_runtime.h>
#include <cuda_bf16.h>

#define NMAX 50000
#define D    96
#define DEG_CAP 128   // Poisson(16) max over 50K nodes << 128

// Scratch (device globals; zero-initialized at load; g_deg reset to 0 by
// gather_kernel after use, so every graph replay sees a clean state)
__device__ int   g_deg[NMAX];
__device__ int   g_adj[NMAX * DEG_CAP];   // padded adjacency (src per dst)
__device__ float g_agg[NMAX * D];         // mean-aggregated neighbor features

// ---------------------------------------------------------------------------
// Kernel 1: build padded adjacency. FOUR edges per thread: two int4 loads,
// then 4 independent atomics + 4 independent stores -> 4x the MLP of the
// 1-edge/thread version (which profiled latency-bound: 16us, issue=4.3%).
// ---------------------------------------------------------------------------
__global__ __launch_bounds__(256)
void fill_kernel(const int* __restrict__ edge_index, int e_total) {
    int t  = blockIdx.x * blockDim.x + threadIdx.x;
    int e0 = t * 4;
    if (e0 >= e_total) return;

    if (((e_total & 3) == 0) && (e0 + 3 < e_total)) {
        int4 s = *(const int4*)(edge_index + e0);
        int4 dd = *(const int4*)(edge_index + e_total + e0);
        int p0 = atomicAdd(&g_deg[dd.x], 1);
        int p1 = atomicAdd(&g_deg[dd.y], 1);
        int p2 = atomicAdd(&g_deg[dd.z], 1);
        int p3 = atomicAdd(&g_deg[dd.w], 1);
        if (p0 < DEG_CAP) g_adj[dd.x * DEG_CAP + p0] = s.x;
        if (p1 < DEG_CAP) g_adj[dd.y * DEG_CAP + p1] = s.y;
        if (p2 < DEG_CAP) g_adj[dd.z * DEG_CAP + p2] = s.z;
        if (p3 < DEG_CAP) g_adj[dd.w * DEG_CAP + p3] = s.w;
    } else {
        for (int e = e0; e < min(e0 + 4, e_total); e++) {
            int src = __ldg(&edge_index[e]);
            int dst = __ldg(&edge_index[e_total + e]);
            int pos = atomicAdd(&g_deg[dst], 1);
            if (pos < DEG_CAP) g_adj[dst * DEG_CAP + pos] = src;
        }
    }
}

// ---------------------------------------------------------------------------
// Kernel 2: gather + mean. One warp per node; lanes 0..23 own one float4
// chunk of the 96-dim row. No smem; launch_bounds(256,4) caps regs at 64 to
// hold 32 warps/SM for L2-latency cover. Resets g_deg for the next replay.
// ---------------------------------------------------------------------------
__global__ __launch_bounds__(256, 4)
void gather_kernel(const float* __restrict__ x, int n_total) {
    int gw   = (blockIdx.x * blockDim.x + threadIdx.x) >> 5;
    int lane = threadIdx.x & 31;
    if (gw >= n_total) return;
    int node = gw;

    int d  = g_deg[node];
    int dc = min(d, DEG_CAP);
    const int* adj = g_adj + (size_t)node * DEG_CAP;

    float4 s0 = make_float4(0.f, 0.f, 0.f, 0.f);
    float4 s1 = make_float4(0.f, 0.f, 0.f, 0.f);

    int nbr = (lane < dc) ? adj[lane] : 0;
    for (int jb = 0; jb < dc; jb += 32) {
        int cnt = min(32, dc - jb);
        int nxt = 0;
        int rem = dc - jb - 32;
        if (rem > 0 && lane < rem) nxt = adj[jb + 32 + lane];

        int j = 0;
        for (; j + 3 < cnt; j += 4) {
            int n0 = __shfl_sync(0xffffffffu, nbr, j);
            int n1 = __shfl_sync(0xffffffffu, nbr, j + 1);
            int n2 = __shfl_sync(0xffffffffu, nbr, j + 2);
            int n3 = __shfl_sync(0xffffffffu, nbr, j + 3);
            if (lane < 24) {
                float4 v0 = ((const float4*)(x + (size_t)n0 * D))[lane];
                float4 v1 = ((const float4*)(x + (size_t)n1 * D))[lane];
                float4 v2 = ((const float4*)(x + (size_t)n2 * D))[lane];
                float4 v3 = ((const float4*)(x + (size_t)n3 * D))[lane];
                s0.x += v0.x; s0.y += v0.y; s0.z += v0.z; s0.w += v0.w;
                s1.x += v1.x; s1.y += v1.y; s1.z += v1.z; s1.w += v1.w;
                s0.x += v2.x; s0.y += v2.y; s0.z += v2.z; s0.w += v2.w;
                s1.x += v3.x; s1.y += v3.y; s1.z += v3.z; s1.w += v3.w;
            }
        }
        for (; j < cnt; j++) {
            int n0 = __shfl_sync(0xffffffffu, nbr, j);
            if (lane < 24) {
                float4 v0 = ((const float4*)(x + (size_t)n0 * D))[lane];
                s0.x += v0.x; s0.y += v0.y; s0.z += v0.z; s0.w += v0.w;
            }
        }
        nbr = nxt;
    }

    float inv = __fdividef(1.f, fmaxf((float)d, 1.f));
    if (lane < 24) {
        float4 r;
        r.x = (s0.x + s1.x) * inv;
        r.y = (s0.y + s1.y) * inv;
        r.z = (s0.z + s1.z) * inv;
        r.w = (s0.w + s1.w) * inv;
        ((float4*)(g_agg + (size_t)node * D))[lane] = r;
    }
    if (lane == 0) g_deg[node] = 0;   // clean state for next replay
}

// ---------------------------------------------------------------------------
// f32x2 helpers (Blackwell packed fp32 — FFMA2 in SASS)
// ---------------------------------------------------------------------------
__device__ __forceinline__ unsigned long long pack2(float lo, float hi) {
    unsigned long long r;
    asm("mov.b64 %0, {%1, %2};" : "=l"(r) : "f"(lo), "f"(hi));
    return r;
}
__device__ __forceinline__ void unpack2(unsigned long long v, float& lo, float& hi) {
    asm("mov.b64 {%0, %1}, %2;" : "=f"(lo), "=f"(hi) : "l"(v));
}
__device__ __forceinline__ void fma2(unsigned long long& acc,
                                     unsigned long long a,
                                     unsigned long long b) {
    asm("fma.rn.f32x2 %0, %1, %2, %0;" : "+l"(acc) : "l"(a), "l"(b));
}

// ---------------------------------------------------------------------------
// Kernel 3: dual GEMM (FFMA2) + bias + ReLU.
// CTA = 64 nodes x 96 outputs, 256 threads. Input tile reloaded per phase
// (agg then x) into one buffer -> 63KB smem, 3 CTAs/SM.
// ---------------------------------------------------------------------------
#define TILE_M 64
#define TM 4
#define TN 6
#define TNP 3           // TN/2 packed pairs
#define IN_STRIDE 100   // floats; %4==0 -> float4-aligned rows, conflict-free
#define W_STRIDE  98    // floats; even -> LDS.64-aligned pairs, conflict-free

__global__ __launch_bounds__(256, 3)
void gemm_kernel(const float* __restrict__ x,
                 const float* __restrict__ Wl,
                 const float* __restrict__ bl,
                 const float* __restrict__ Wr,
                 float* __restrict__ out,
                 int n_total) {
    __shared__ float sIn[TILE_M * IN_STRIDE];  // 25.6 KB, reused per phase
    __shared__ float sW[D * W_STRIDE];         // 37.6 KB, reloaded per phase

    const int tid  = threadIdx.x;
    const int base = blockIdx.x * TILE_M;

    const int tx = tid & 15;
    const int ty = tid >> 4;
    const int o0 = tx * TN;    // even -> 8B-aligned W pairs
    const int m0 = ty * TM;

    unsigned long long acc[TM][TNP];
#pragma unroll
    for (int i = 0; i < TM; i++)
#pragma unroll
        for (int p = 0; p < TNP; p++) acc[i][p] = 0ull;

#pragma unroll 1
    for (int phase = 0; phase < 2; phase++) {
        const float* W  = (phase == 0) ? Wl : Wr;
        const float* In = (phase == 0) ? g_agg : x;

        __syncthreads();   // phase 1: previous compute done before overwrite

        // load input tile (coalesced float4)
        for (int i = tid; i < TILE_M * (D / 4); i += 256) {
            int m = i / 24;
            int c = i - m * 24;
            int node = base + m;
            float4 v = make_float4(0.f, 0.f, 0.f, 0.f);
            if (node < n_total)
                v = ((const float4*)(In + (size_t)node * D))[c];
            *(float4*)&sIn[m * IN_STRIDE + c * 4] = v;
        }
        // load W transposed: sW[k][o] = W[o*D + k]
        for (int i = tid; i < D * D; i += 256) {
            int o = i / D;
            int k = i - o * D;
            sW[k * W_STRIDE + o] = W[i];
        }
        __syncthreads();

#pragma unroll 2
        for (int k = 0; k < D; k += 4) {
            float4 av[TM];
#pragma unroll
            for (int i = 0; i < TM; i++)
                av[i] = *(const float4*)&sIn[(m0 + i) * IN_STRIDE + k];

#pragma unroll
            for (int kk = 0; kk < 4; kk++) {
                const float* wr = &sW[(k + kk) * W_STRIDE + o0];
                unsigned long long w0 = *(const unsigned long long*)(wr);
                unsigned long long w1 = *(const unsigned long long*)(wr + 2);
                unsigned long long w2 = *(const unsigned long long*)(wr + 4);
#pragma unroll
                for (int i = 0; i < TM; i++) {
                    float a = (kk == 0) ? av[i].x : (kk == 1) ? av[i].y
                            : (kk == 2) ? av[i].z : av[i].w;
                    unsigned long long aa = pack2(a, a);
                    fma2(acc[i][0], aa, w0);
                    fma2(acc[i][1], aa, w1);
                    fma2(acc[i][2], aa, w2);
                }
            }
        }
    }

    // epilogue: bias + relu + store
    float b[TN];
#pragma unroll
    for (int j = 0; j < TN; j++) b[j] = __ldg(&bl[o0 + j]);

#pragma unroll
    for (int i = 0; i < TM; i++) {
        int node = base + m0 + i;
        if (node < n_total) {
            float r[TN];
#pragma unroll
            for (int p = 0; p < TNP; p++)
                unpack2(acc[i][p], r[2 * p], r[2 * p + 1]);
            float* op = out + (size_t)node * D + o0;
#pragma unroll
            for (int j = 0; j < TN; j++)
                op[j] = fmaxf(r[j] + b[j], 0.f);
        }
    }
}

// ---------------------------------------------------------------------------
extern "C" void kernel_launch(void* const* d_in, const int* in_sizes, int n_in,
                              void* d_out, int out_size) {
    const float* x   = (const float*)d_in[0];   // [N, 96]
    const int*   ei  = (const int*)d_in[1];     // [2, E]
    const float* Wl  = (const float*)d_in[2];   // [96, 96]
    const float* bl  = (const float*)d_in[3];   // [96]
    const float* Wr  = (const float*)d_in[4];   // [96, 96]
    float* out = (float*)d_out;

    int n = in_sizes[0] / D;
    int e = in_sizes[1] / 2;

    int fill_threads = (e + 3) / 4;
    fill_kernel<<<(fill_threads + 255) / 256, 256>>>(ei, e);
    gather_kernel<<<(n * 32 + 255) / 256, 256>>>(x, n);
    gemm_kernel<<<(n + TILE_M - 1) / TILE_M, 256>>>(x, Wl, bl, Wr, out, n);
}